// round 2
// baseline (speedup 1.0000x reference)
#include <cuda_runtime.h>
#include <cuda_bf16.h>
#include <stdint.h>

// Problem geometry (fixed by reference: frames (4,8,2,4,480,640) f32)
#define Bb 4
#define Ss 8
#define Cc 8
#define Hh 480
#define Ww 640
#define HW (Hh*Ww)               // 307200
#define BS (Bb*Ss)               // 32
#define NPIX (BS*HW)             // 9,830,400
#define MAXP 200000
#define FEAT_ELEMS (MAXP*Cc)     // 1,600,000
#define COORD_ELEMS (MAXP*4)     // 800,000
#define OUT_ELEMS (FEAT_ELEMS + COORD_ELEMS)  // 2,400,000
#define THRESH 3.0f

#define NB 512
#define TPB 256
#define CHUNK (NPIX/NB)          // 19200 (divides HW: 307200/19200 = 16 -> chunk within one frame)
#define ITERS (CHUNK/TPB)        // 75

// Scratch (static device globals -- no runtime allocation)
__device__ unsigned g_bitmap[NPIX/32];   // 307200 words = 1.2 MB
__device__ int g_blockCnt[NB];
__device__ int g_blockOff[NB+1];

// ---------------------------------------------------------------------------
// Kernel 0: zero the whole output (harness poisons it to 0xAA)
// ---------------------------------------------------------------------------
__global__ void k_zero(float* __restrict__ out) {
    int i = blockIdx.x * blockDim.x + threadIdx.x;   // float4 index
    const int n4 = OUT_ELEMS / 4;                    // 600,000
    if (i < n4) ((float4*)out)[i] = make_float4(0.f, 0.f, 0.f, 0.f);
}

// ---------------------------------------------------------------------------
// Kernel 1: compute mask bitmap + per-block counts (streams all 314.6 MB)
// ---------------------------------------------------------------------------
__global__ void __launch_bounds__(TPB) k_mask(const float* __restrict__ frames) {
    const int b = blockIdx.x;
    const long chunkStart = (long)b * CHUNK;
    const int bf = (int)(chunkStart / HW);           // constant within block
    const int rem0 = (int)(chunkStart % HW);
    const float* __restrict__ base = frames + (size_t)bf * Cc * HW;

    const int tid  = threadIdx.x;
    const int lane = tid & 31;
    const int warp = tid >> 5;

    unsigned warpCnt = 0;

    for (int it = 0; it < ITERS; ++it) {
        const int rem = rem0 + it * TPB + tid;
        float m = 0.f;
        #pragma unroll
        for (int c = 0; c < Cc; ++c)
            m = fmaxf(m, fabsf(__ldg(base + (size_t)c * HW + rem)));
        unsigned bal = __ballot_sync(0xffffffffu, m > THRESH);
        if (lane == 0) {
            g_bitmap[(unsigned)((chunkStart + it * TPB + warp * 32) >> 5)] = bal;
            warpCnt += (unsigned)__popc(bal);
        }
    }

    __shared__ int sW[TPB / 32];
    if (lane == 0) sW[warp] = (int)warpCnt;
    __syncthreads();
    if (tid == 0) {
        int t = 0;
        #pragma unroll
        for (int i = 0; i < TPB / 32; ++i) t += sW[i];
        g_blockCnt[b] = t;
    }
}

// ---------------------------------------------------------------------------
// Kernel 2: exclusive scan of the 512 block counts (single block)
// ---------------------------------------------------------------------------
__global__ void k_scan() {
    __shared__ int sh[NB];
    const int tid = threadIdx.x;                      // launched with NB threads
    const int v0 = g_blockCnt[tid];
    sh[tid] = v0;
    __syncthreads();
    // Hillis-Steele inclusive scan
    for (int off = 1; off < NB; off <<= 1) {
        int v = (tid >= off) ? sh[tid - off] : 0;
        __syncthreads();
        sh[tid] += v;
        __syncthreads();
    }
    g_blockOff[tid] = sh[tid] - v0;                   // exclusive
    if (tid == NB - 1) g_blockOff[NB] = sh[tid];      // total
}

// ---------------------------------------------------------------------------
// Kernel 3: ranked write of coords + gathered features
// ---------------------------------------------------------------------------
__global__ void __launch_bounds__(TPB) k_write(const float* __restrict__ frames,
                                               float* __restrict__ out) {
    const int b = blockIdx.x;
    const long chunkStart = (long)b * CHUNK;
    const int bf = (int)(chunkStart / HW);
    const int rem0 = (int)(chunkStart % HW);
    const float* __restrict__ base = frames + (size_t)bf * Cc * HW;

    const int tid  = threadIdx.x;
    const int lane = tid & 31;
    const int warp = tid >> 5;

    const float fbatch = (float)(bf / Ss);
    const float ftime  = (float)(bf % Ss);

    __shared__ int sW[TPB / 32];
    int run = g_blockOff[b];                          // running global rank base

    float* __restrict__ outFeat  = out;
    float* __restrict__ outCoord = out + FEAT_ELEMS;

    for (int it = 0; it < ITERS; ++it) {
        const unsigned w =
            g_bitmap[(unsigned)((chunkStart + it * TPB + warp * 32) >> 5)];
        if (lane == 0) sW[warp] = __popc(w);
        __syncthreads();

        int warpOff = 0, total = 0;
        #pragma unroll
        for (int i = 0; i < TPB / 32; ++i) {
            int c = sW[i];
            if (i < warp) warpOff += c;
            total += c;
        }

        const bool bit = (w >> lane) & 1u;
        if (bit) {
            const int rank = run + warpOff + __popc(w & ((1u << lane) - 1u));
            if (rank < MAXP) {
                const int rem = rem0 + it * TPB + tid;
                const int y = rem / Ww;
                const int x = rem - y * Ww;
                // coords: (batch, time, y, x) as one float4
                ((float4*)outCoord)[rank] =
                    make_float4(fbatch, ftime, (float)y, (float)x);
                // features: 8 channels, two float4 stores
                float4 f0, f1;
                f0.x = __ldg(base + 0 * (size_t)HW + rem);
                f0.y = __ldg(base + 1 * (size_t)HW + rem);
                f0.z = __ldg(base + 2 * (size_t)HW + rem);
                f0.w = __ldg(base + 3 * (size_t)HW + rem);
                f1.x = __ldg(base + 4 * (size_t)HW + rem);
                f1.y = __ldg(base + 5 * (size_t)HW + rem);
                f1.z = __ldg(base + 6 * (size_t)HW + rem);
                f1.w = __ldg(base + 7 * (size_t)HW + rem);
                ((float4*)outFeat)[rank * 2 + 0] = f0;
                ((float4*)outFeat)[rank * 2 + 1] = f1;
            }
        }
        __syncthreads();   // protect sW before next iteration overwrites it
        run += total;
    }
}

// ---------------------------------------------------------------------------
extern "C" void kernel_launch(void* const* d_in, const int* in_sizes, int n_in,
                              void* d_out, int out_size) {
    const float* frames = (const float*)d_in[0];
    float* out = (float*)d_out;

    // 1) zero output
    {
        const int n4 = OUT_ELEMS / 4;
        k_zero<<<(n4 + 255) / 256, 256>>>(out);
    }
    // 2) mask + per-block counts
    k_mask<<<NB, TPB>>>(frames);
    // 3) exclusive scan of block counts
    k_scan<<<1, NB>>>();
    // 4) ranked writes
    k_write<<<NB, TPB>>>(frames, out);
}

// round 4
// speedup vs baseline: 1.7654x; 1.7654x over previous
#include <cuda_runtime.h>
#include <cuda_bf16.h>
#include <stdint.h>

// Problem geometry (fixed: frames (4,8,2,4,480,640) f32)
#define Bb 4
#define Ss 8
#define Cc 8
#define Hh 480
#define Ww 640
#define HW (Hh*Ww)               // 307200
#define BS (Bb*Ss)               // 32
#define NPIX (BS*HW)             // 9,830,400
#define MAXP 200000
#define FEAT_ELEMS (MAXP*Cc)     // 1,600,000
#define COORD_ELEMS (MAXP*4)     // 800,000
#define OUT_ELEMS (FEAT_ELEMS + COORD_ELEMS)
#define THRESH 3.0f

// Decomposition: 1920 chunks of 5120 pixels (= 160 bitmap words).
// 5120 divides HW (307200/5120 = 60), so a chunk never crosses a frame.
#define NB 1920
#define CHUNK 5120
#define WORDS_PER_CHUNK 160      // CHUNK/32
#define TPB_MASK 256
#define ITERS_MASK (CHUNK/TPB_MASK)   // 20
#define TPB_WRITE 160            // one thread per bitmap word
#define TPB_SCAN 480             // 480 threads x 4 counts = 1920

// Scratch (static device globals)
__device__ unsigned g_bitmap[NPIX/32];   // 307200 words = 1.2 MB
__device__ int g_blockCnt[NB];
__device__ int g_blockOff[NB];

// ---------------------------------------------------------------------------
// Kernel 0: zero the output (harness poisons to 0xAA; tail entries must be 0)
// ---------------------------------------------------------------------------
__global__ void k_zero(float* __restrict__ out) {
    int i = blockIdx.x * blockDim.x + threadIdx.x;   // float4 index
    const int n4 = OUT_ELEMS / 4;
    if (i < n4) ((float4*)out)[i] = make_float4(0.f, 0.f, 0.f, 0.f);
}

// ---------------------------------------------------------------------------
// Kernel 1: mask bitmap + per-chunk counts (streams all 314.6 MB)
// ---------------------------------------------------------------------------
__global__ void __launch_bounds__(TPB_MASK) k_mask(const float* __restrict__ frames) {
    const int b = blockIdx.x;
    const long chunkStart = (long)b * CHUNK;
    const int bf = (int)(chunkStart / HW);           // constant within block
    const int rem0 = (int)(chunkStart % HW);
    const float* __restrict__ base = frames + (size_t)bf * Cc * HW;

    const int tid  = threadIdx.x;
    const int lane = tid & 31;
    const int warp = tid >> 5;

    unsigned warpCnt = 0;

    #pragma unroll 4
    for (int it = 0; it < ITERS_MASK; ++it) {
        const int rem = rem0 + it * TPB_MASK + tid;
        float m = 0.f;
        #pragma unroll
        for (int c = 0; c < Cc; ++c)
            m = fmaxf(m, fabsf(__ldg(base + (size_t)c * HW + rem)));
        unsigned bal = __ballot_sync(0xffffffffu, m > THRESH);
        if (lane == 0) {
            g_bitmap[(unsigned)((chunkStart + it * TPB_MASK + warp * 32) >> 5)] = bal;
            warpCnt += (unsigned)__popc(bal);
        }
    }

    __shared__ int sW[TPB_MASK / 32];
    if (lane == 0) sW[warp] = (int)warpCnt;
    __syncthreads();
    if (tid == 0) {
        int t = 0;
        #pragma unroll
        for (int i = 0; i < TPB_MASK / 32; ++i) t += sW[i];
        g_blockCnt[b] = t;
    }
}

// ---------------------------------------------------------------------------
// Kernel 2: exclusive scan of 1920 chunk counts (single block, 480 threads x 4)
// ---------------------------------------------------------------------------
__global__ void __launch_bounds__(TPB_SCAN) k_scan() {
    __shared__ int sh[TPB_SCAN];
    const int t = threadIdx.x;
    int c0 = g_blockCnt[t*4+0];
    int c1 = g_blockCnt[t*4+1];
    int c2 = g_blockCnt[t*4+2];
    int c3 = g_blockCnt[t*4+3];
    const int s = c0 + c1 + c2 + c3;
    sh[t] = s;
    __syncthreads();
    for (int off = 1; off < TPB_SCAN; off <<= 1) {
        int v = (t >= off) ? sh[t - off] : 0;
        __syncthreads();
        sh[t] += v;
        __syncthreads();
    }
    int run = sh[t] - s;   // exclusive prefix of this thread's group
    g_blockOff[t*4+0] = run; run += c0;
    g_blockOff[t*4+1] = run; run += c1;
    g_blockOff[t*4+2] = run; run += c2;
    g_blockOff[t*4+3] = run;
}

// ---------------------------------------------------------------------------
// Kernel 3: ranked write — one thread per bitmap word, single block scan
// ---------------------------------------------------------------------------
__global__ void __launch_bounds__(TPB_WRITE) k_write(const float* __restrict__ frames,
                                                     float* __restrict__ out) {
    const int b = blockIdx.x;
    const int t = threadIdx.x;
    const int lane = t & 31;
    const int warp = t >> 5;

    unsigned w = g_bitmap[b * WORDS_PER_CHUNK + t];
    const int cnt = __popc(w);

    // warp inclusive scan of counts
    int inc = cnt;
    #pragma unroll
    for (int o = 1; o < 32; o <<= 1) {
        int v = __shfl_up_sync(0xffffffffu, inc, o);
        if (lane >= o) inc += v;
    }
    __shared__ int sW[TPB_WRITE / 32];   // 5 warps
    if (lane == 31) sW[warp] = inc;
    __syncthreads();
    int wOff = 0;
    #pragma unroll
    for (int i = 0; i < TPB_WRITE / 32; ++i)
        if (i < warp) wOff += sW[i];

    int rank = g_blockOff[b] + wOff + (inc - cnt);   // global rank of my first bit
    if (w == 0u || rank >= MAXP) return;

    const long chunkStart = (long)b * CHUNK;
    const int bf = (int)(chunkStart / HW);           // chunk is within one frame
    const float* __restrict__ base = frames + (size_t)bf * Cc * HW;
    const int rem0 = (int)(chunkStart - (long)bf * HW) + t * 32;

    const float fbatch = (float)(bf / Ss);
    const float ftime  = (float)(bf % Ss);

    float* __restrict__ outFeat  = out;
    float* __restrict__ outCoord = out + FEAT_ELEMS;

    while (w) {
        const int bit = __ffs(w) - 1;
        w &= w - 1u;
        if (rank >= MAXP) break;
        const int rem = rem0 + bit;
        const int y = rem / Ww;
        const int x = rem - y * Ww;

        float4 f0, f1;
        f0.x = __ldg(base + 0 * (size_t)HW + rem);
        f0.y = __ldg(base + 1 * (size_t)HW + rem);
        f0.z = __ldg(base + 2 * (size_t)HW + rem);
        f0.w = __ldg(base + 3 * (size_t)HW + rem);
        f1.x = __ldg(base + 4 * (size_t)HW + rem);
        f1.y = __ldg(base + 5 * (size_t)HW + rem);
        f1.z = __ldg(base + 6 * (size_t)HW + rem);
        f1.w = __ldg(base + 7 * (size_t)HW + rem);

        ((float4*)outCoord)[rank] = make_float4(fbatch, ftime, (float)y, (float)x);
        ((float4*)outFeat)[rank * 2 + 0] = f0;
        ((float4*)outFeat)[rank * 2 + 1] = f1;
        ++rank;
    }
}

// ---------------------------------------------------------------------------
extern "C" void kernel_launch(void* const* d_in, const int* in_sizes, int n_in,
                              void* d_out, int out_size) {
    const float* frames = (const float*)d_in[0];
    float* out = (float*)d_out;

    {
        const int n4 = OUT_ELEMS / 4;
        k_zero<<<(n4 + 255) / 256, 256>>>(out);
    }
    k_mask<<<NB, TPB_MASK>>>(frames);
    k_scan<<<1, TPB_SCAN>>>();
    k_write<<<NB, TPB_WRITE>>>(frames, out);
}

// round 7
// speedup vs baseline: 2.5038x; 1.4182x over previous
#include <cuda_runtime.h>
#include <cuda_bf16.h>
#include <stdint.h>

// Problem geometry (fixed: frames (4,8,2,4,480,640) f32)
#define Bb 4
#define Ss 8
#define Cc 8
#define Hh 480
#define Ww 640
#define HW (Hh*Ww)               // 307200
#define NPIX (32*HW)             // 9,830,400
#define MAXP 200000
#define FEAT_ELEMS (MAXP*Cc)     // 1,600,000
#define OUT_ELEMS (FEAT_ELEMS + MAXP*4)
#define THRESH 3.0f

// One block = one 4096-pixel chunk (within a single frame: 307200/4096 = 75)
#define TPB 512
#define PITER 4                  // pixels per thread per iteration (float4)
#define ITERS 2
#define CHUNK (TPB*PITER*ITERS)  // 4096
#define NB (NPIX/CHUNK)          // 2400
#define NWORDS (CHUNK/32)        // 128

// Decoupled-lookback tile state: bits[1:0] flag (0=invalid,1=partial,2=inclusive),
// bits[31:2] value.
__device__ unsigned g_tile[NB];
__device__ int g_total;

// ---------------------------------------------------------------------------
// Kernel 0: reset tile flags + total
// ---------------------------------------------------------------------------
__global__ void k_reset() {
    int i = blockIdx.x * blockDim.x + threadIdx.x;
    if (i < NB) g_tile[i] = 0u;
    if (i == 0) g_total = 0;
}

// ---------------------------------------------------------------------------
// Kernel 1: fused mask + single-pass scan (decoupled lookback) + ranked write
// ---------------------------------------------------------------------------
__global__ void __launch_bounds__(TPB) k_fused(const float* __restrict__ frames,
                                               float* __restrict__ out) {
    const int b    = blockIdx.x;
    const int tid  = threadIdx.x;
    const int lane = tid & 31;
    const int warp = tid >> 5;

    const long chunkStart = (long)b * CHUNK;
    const int bf   = (int)(chunkStart / HW);
    const int rem0 = (int)(chunkStart % HW);
    const float* __restrict__ base = frames + (size_t)bf * Cc * HW;

    __shared__ unsigned sBits[NWORDS];
    __shared__ int sWp[NWORDS];      // per-word exclusive prefix within 32-word group
    __shared__ int sGsum[4];         // group totals (4 groups of 32 words)
    __shared__ int sWarp[TPB / 32];
    __shared__ int sExcl;

    // ---------------- Phase A: mask + bitmap in smem ----------------
    int myPartial = 0;               // popc, held by oct leaders only
    #pragma unroll
    for (int it = 0; it < ITERS; ++it) {
        const int pix = rem0 + it * (TPB * PITER) + tid * PITER;
        float mx = 0.f, my = 0.f, mz = 0.f, mw = 0.f;
        #pragma unroll
        for (int c = 0; c < Cc; ++c) {
            float4 v = __ldg((const float4*)(base + (size_t)c * HW + pix));
            mx = fmaxf(mx, fabsf(v.x));
            my = fmaxf(my, fabsf(v.y));
            mz = fmaxf(mz, fabsf(v.z));
            mw = fmaxf(mw, fabsf(v.w));
        }
        unsigned nib = (unsigned)(mx > THRESH)
                     | ((unsigned)(my > THRESH) << 1)
                     | ((unsigned)(mz > THRESH) << 2)
                     | ((unsigned)(mw > THRESH) << 3);
        unsigned val = nib << ((lane & 7) * 4);
        val |= __shfl_xor_sync(0xffffffffu, val, 1);
        val |= __shfl_xor_sync(0xffffffffu, val, 2);
        val |= __shfl_xor_sync(0xffffffffu, val, 4);
        if ((lane & 7) == 0) {
            sBits[it * 64 + warp * 4 + (lane >> 3)] = val;
            myPartial += __popc(val);
        }
    }
    int warpSum = __reduce_add_sync(0xffffffffu, myPartial);
    if (lane == 0) sWarp[warp] = warpSum;
    __syncthreads();   // sBits + sWarp complete

    // ---------------- warp 0: publish + lookback; warps 1-4: word scan ------
    if (warp == 0) {
        int v = (lane < TPB / 32) ? sWarp[lane] : 0;
        int cnt = __reduce_add_sync(0xffffffffu, v);

        if (lane == 0) {
            unsigned pub = ((unsigned)cnt << 2) | (b == 0 ? 2u : 1u);
            atomicExch(&g_tile[b], pub);
        }
        int excl = 0;
        if (b > 0) {
            int idx = b - 1;
            for (;;) {
                const int my_i = idx - lane;
                unsigned t = 2u;   // out-of-range: inclusive, value 0
                if (my_i >= 0) {
                    t = *((volatile unsigned*)&g_tile[my_i]);
                    while ((t & 3u) == 0u) {
                        __nanosleep(40);
                        t = *((volatile unsigned*)&g_tile[my_i]);
                    }
                }
                unsigned ball = __ballot_sync(0xffffffffu, (t & 3u) == 2u);
                if (ball) {
                    const int L = __ffs(ball) - 1;   // closest inclusive tile
                    int contrib = (lane <= L) ? (int)(t >> 2) : 0;
                    excl += __reduce_add_sync(0xffffffffu, contrib);
                    break;
                } else {
                    excl += __reduce_add_sync(0xffffffffu, (int)(t >> 2));
                    idx -= 32;
                }
            }
        }
        if (lane == 0) {
            sExcl = excl;
            if (b > 0) atomicExch(&g_tile[b], ((unsigned)(cnt + excl) << 2) | 2u);
            if (b == NB - 1) g_total = cnt + excl;
        }
    } else if (warp <= 4) {
        // exclusive scan of the 128 word-popcounts (4 groups of 32)
        const int g = warp - 1;
        const int i = g * 32 + lane;
        int p = __popc(sBits[i]);
        int inc = p;
        #pragma unroll
        for (int o = 1; o < 32; o <<= 1) {
            int s = __shfl_up_sync(0xffffffffu, inc, o);
            if (lane >= o) inc += s;
        }
        sWp[i] = inc - p;
        if (lane == 31) sGsum[g] = inc;
    }
    __syncthreads();

    // ---------------- Phase B: ranked writes (gather hits L1/L2) ------------
    const int excl = sExcl;
    const float fbatch = (float)(bf / Ss);
    const float ftime  = (float)(bf % Ss);
    float* __restrict__ outFeat  = out;
    float* __restrict__ outCoord = out + FEAT_ELEMS;

    #pragma unroll
    for (int it = 0; it < ITERS; ++it) {
        const int wi = it * 64 + warp * 4 + (lane >> 3);
        const unsigned w = sBits[wi];
        const unsigned shift = (lane & 7) * 4;
        if ((w >> shift) & 0xFu) {
            int gp = 0;
            const int grp = wi >> 5;
            #pragma unroll
            for (int g = 0; g < 4; ++g) if (g < grp) gp += sGsum[g];
            const int wordBase = excl + gp + sWp[wi];
            const int pix0 = rem0 + it * (TPB * PITER) + tid * PITER;
            #pragma unroll
            for (int j = 0; j < PITER; ++j) {
                if (w & (1u << (shift + j))) {
                    const int rank = wordBase +
                        __popc(w & ((1u << (shift + j)) - 1u));
                    if (rank < MAXP) {
                        const int rem = pix0 + j;
                        const int y = rem / Ww;
                        const int x = rem - y * Ww;
                        float4 f0, f1;
                        f0.x = __ldg(base + 0 * (size_t)HW + rem);
                        f0.y = __ldg(base + 1 * (size_t)HW + rem);
                        f0.z = __ldg(base + 2 * (size_t)HW + rem);
                        f0.w = __ldg(base + 3 * (size_t)HW + rem);
                        f1.x = __ldg(base + 4 * (size_t)HW + rem);
                        f1.y = __ldg(base + 5 * (size_t)HW + rem);
                        f1.z = __ldg(base + 6 * (size_t)HW + rem);
                        f1.w = __ldg(base + 7 * (size_t)HW + rem);
                        ((float4*)outCoord)[rank] =
                            make_float4(fbatch, ftime, (float)y, (float)x);
                        ((float4*)outFeat)[rank * 2 + 0] = f0;
                        ((float4*)outFeat)[rank * 2 + 1] = f1;
                    }
                }
            }
        }
    }
}

// ---------------------------------------------------------------------------
// Kernel 2: zero the tail [n_valid, MAXP) (no-op when hits >= MAXP)
// ---------------------------------------------------------------------------
__global__ void k_tail(float* __restrict__ out) {
    const int i = blockIdx.x * blockDim.x + threadIdx.x;
    int nv = g_total;
    if (nv > MAXP) nv = MAXP;
    if (i >= nv && i < MAXP) {
        const float4 z = make_float4(0.f, 0.f, 0.f, 0.f);
        ((float4*)(out + FEAT_ELEMS))[i] = z;
        ((float4*)out)[i * 2 + 0] = z;
        ((float4*)out)[i * 2 + 1] = z;
    }
}

// ---------------------------------------------------------------------------
extern "C" void kernel_launch(void* const* d_in, const int* in_sizes, int n_in,
                              void* d_out, int out_size) {
    const float* frames = (const float*)d_in[0];
    float* out = (float*)d_out;

    k_reset<<<(NB + 255) / 256, 256>>>();
    k_fused<<<NB, TPB>>>(frames, out);
    k_tail<<<(MAXP + 255) / 256, 256>>>(out);
}